// round 15
// baseline (speedup 1.0000x reference)
#include <cuda_runtime.h>
#include <cuda_bf16.h>
#include <math.h>

#define NN 100000
#define EE 1600000

#define SCAN_BS 512
#define SCAN_NB ((NN + SCAN_BS - 1) / SCAN_BS)   // 196

// ---------------- scratch (device globals; no allocation allowed) ----------------
__device__ float  g_deg[NN];
__device__ float  g_dinv[NN];
__device__ int    g_cnt[NN];
__device__ int    g_ptr[NN];
__device__ int    g_cur[NN];
__device__ int    g_bsum[SCAN_NB];
__device__ int    g_boff[SCAN_NB];
__device__ int2   g_edge[EE];       // CSR slot: {src, float_bits(norm)}
__device__ float4 g_h4[NN * 16];    // GEMM output (messages)
__device__ float4 g_gc4[NN * 16];   // aggregated + activated output

// ---------------- fast activations (2-ulp class, saturation-safe) ----------------
__device__ __forceinline__ float f_sig(float x) {
    return __fdividef(1.0f, 1.0f + __expf(-x));
}
__device__ __forceinline__ float f_tanh(float x) {
    return 1.0f - __fdividef(2.0f, __expf(2.0f * x) + 1.0f);
}

// ---------------- cp.async helpers ----------------
__device__ __forceinline__ void cp_async16(void* smem_dst, const void* gsrc) {
    unsigned s = (unsigned)__cvta_generic_to_shared(smem_dst);
    asm volatile("cp.async.cg.shared.global [%0], [%1], 16;" :: "r"(s), "l"(gsrc));
}
__device__ __forceinline__ void cp_commit() {
    asm volatile("cp.async.commit_group;");
}
__device__ __forceinline__ void cp_wait0() {
    asm volatile("cp.async.wait_group 0;");
}

// ---------------- prep ----------------
__global__ void k_init() {
    int i = blockIdx.x * blockDim.x + threadIdx.x;
    if (i < NN) { g_deg[i] = 1.0f; g_cnt[i] = 0; }
}

__global__ void k_count(const int* __restrict__ ei, const float* __restrict__ w) {
    int p = blockIdx.x * blockDim.x + threadIdx.x;
    if (p < EE / 2) {
        int2   c2 = __ldg((const int2*)(ei + EE) + p);
        float2 w2 = __ldg((const float2*)w + p);
        atomicAdd(&g_deg[c2.x], w2.x);
        atomicAdd(&g_cnt[c2.x], 1);
        atomicAdd(&g_deg[c2.y], w2.y);
        atomicAdd(&g_cnt[c2.y], 1);
    }
}

__global__ __launch_bounds__(SCAN_BS) void k_scan1() {
    __shared__ int sh[SCAN_BS];
    int t = threadIdx.x;
    int i = blockIdx.x * SCAN_BS + t;
    if (i < NN) {
        float d = g_deg[i];
        g_dinv[i] = (d > 0.0f) ? rsqrtf(d) : 0.0f;
    }
    int v = (i < NN) ? g_cnt[i] : 0;
    sh[t] = v;
    __syncthreads();
#pragma unroll
    for (int off = 1; off < SCAN_BS; off <<= 1) {
        int x = (t >= off) ? sh[t - off] : 0;
        __syncthreads();
        sh[t] += x;
        __syncthreads();
    }
    if (i < NN) g_ptr[i] = sh[t] - v;
    if (t == SCAN_BS - 1) g_bsum[blockIdx.x] = sh[t];
}

__global__ __launch_bounds__(256) void k_scan2() {
    __shared__ int sh[256];
    int t = threadIdx.x;
    int v = (t < SCAN_NB) ? g_bsum[t] : 0;
    sh[t] = v;
    __syncthreads();
#pragma unroll
    for (int off = 1; off < 256; off <<= 1) {
        int x = (t >= off) ? sh[t - off] : 0;
        __syncthreads();
        sh[t] += x;
        __syncthreads();
    }
    if (t < SCAN_NB) g_boff[t] = sh[t] - v;
}

__global__ __launch_bounds__(SCAN_BS) void k_scan3() {
    int i = blockIdx.x * SCAN_BS + threadIdx.x;
    if (i < NN) {
        int p = g_ptr[i] + g_boff[blockIdx.x];
        g_ptr[i] = p;
        g_cur[i] = p;
    }
}

__global__ void k_scatter(const int* __restrict__ ei, const float* __restrict__ w) {
    int p = blockIdx.x * blockDim.x + threadIdx.x;
    if (p < EE / 2) {
        int2   r2 = __ldg((const int2*)ei + p);
        int2   c2 = __ldg((const int2*)(ei + EE) + p);
        float2 w2 = __ldg((const float2*)w + p);
        float n0 = g_dinv[r2.x] * w2.x * g_dinv[c2.x];
        float n1 = g_dinv[r2.y] * w2.y * g_dinv[c2.y];
        int s0 = atomicAdd(&g_cur[c2.x], 1);
        int s1 = atomicAdd(&g_cur[c2.y], 1);
        g_edge[s0] = make_int2(r2.x, __float_as_int(n0));
        g_edge[s1] = make_int2(r2.y, __float_as_int(n1));
    }
}

// ---------------- dense GEMM: cp.async double-buffered smem pipeline ----------------
// R13 profile: 47.5us, fma=23.8%, issue=39.4% — load latency + 2 syncs/tile exposed.
// Fix: prefetch tile t+stride via LDGSTS while computing tile t; 1 sync/tile.
__device__ __forceinline__ void gemm64_body(const float* __restrict__ x,
                                            const float* __restrict__ W) {
    int t   = threadIdx.x;
    int c   = t & 63;
    int sub = t >> 6;                 // 0..3
    float w[64];
#pragma unroll
    for (int k = 0; k < 64; k++) w[k] = __ldg(&W[k * 64 + c]);

    __shared__ float4 s_x[2][16][16]; // 2 x (16 rows x 64 floats)

    float* __restrict__ hout = (float*)g_h4;
    const int tiles = NN / 16;        // 6250
    int row16 = t >> 4, col16 = t & 15;

    int tile = blockIdx.x;
    if (tile < tiles)
        cp_async16(&s_x[0][row16][col16],
                   (const float4*)(x + (size_t)(tile * 16 + row16) * 64) + col16);
    cp_commit();

    int buf = 0;
    for (; tile < tiles; tile += gridDim.x) {
        cp_wait0();
        __syncthreads();               // buffer `buf` filled; prev compute on buf^1 done
        int next = tile + gridDim.x;
        if (next < tiles)
            cp_async16(&s_x[buf ^ 1][row16][col16],
                       (const float4*)(x + (size_t)(next * 16 + row16) * 64) + col16);
        cp_commit();

        float acc[4] = {0.0f, 0.0f, 0.0f, 0.0f};
#pragma unroll
        for (int k4 = 0; k4 < 16; k4++) {
#pragma unroll
            for (int rr = 0; rr < 4; rr++) {
                float4 v = s_x[buf][sub + rr * 4][k4];   // LDS broadcast
                acc[rr] = fmaf(v.x, w[4 * k4 + 0], acc[rr]);
                acc[rr] = fmaf(v.y, w[4 * k4 + 1], acc[rr]);
                acc[rr] = fmaf(v.z, w[4 * k4 + 2], acc[rr]);
                acc[rr] = fmaf(v.w, w[4 * k4 + 3], acc[rr]);
            }
        }
        int base = tile * 16;
#pragma unroll
        for (int rr = 0; rr < 4; rr++)
            hout[(size_t)(base + sub + rr * 4) * 64 + c] = acc[rr];
        buf ^= 1;
    }
}

__global__ __launch_bounds__(256) void k_gemm_x(const float* __restrict__ x,
                                                const float* __restrict__ W) {
    gemm64_body(x, W);
}

__global__ __launch_bounds__(256) void k_gemm_gc(const float* __restrict__ W) {
    gemm64_body((const float*)g_gc4, W);
}

// ---------------- fused aggregation (R9, L2-BW bound) ----------------
__global__ __launch_bounds__(256) void k_gather(const float* __restrict__ b, int relu) {
    int t = blockIdx.x * blockDim.x + threadIdx.x;
    int node = t >> 4;
    if (node >= NN) return;
    int l16 = t & 15;

    float s = g_dinv[node];
    s = s * s;
    float4 acc = g_h4[(size_t)node * 16 + l16];
    acc.x *= s; acc.y *= s; acc.z *= s; acc.w *= s;

    int j   = g_ptr[node];
    int end = g_cur[node];

    for (; j + 3 < end; j += 4) {
        int2 e0 = __ldg(&g_edge[j]);
        int2 e1 = __ldg(&g_edge[j + 1]);
        int2 e2 = __ldg(&g_edge[j + 2]);
        int2 e3 = __ldg(&g_edge[j + 3]);
        float4 v0 = __ldg(&g_h4[(size_t)e0.x * 16 + l16]);
        float4 v1 = __ldg(&g_h4[(size_t)e1.x * 16 + l16]);
        float4 v2 = __ldg(&g_h4[(size_t)e2.x * 16 + l16]);
        float4 v3 = __ldg(&g_h4[(size_t)e3.x * 16 + l16]);
        float n0 = __int_as_float(e0.y), n1 = __int_as_float(e1.y);
        float n2 = __int_as_float(e2.y), n3 = __int_as_float(e3.y);
        acc.x = fmaf(n0, v0.x, acc.x); acc.y = fmaf(n0, v0.y, acc.y);
        acc.z = fmaf(n0, v0.z, acc.z); acc.w = fmaf(n0, v0.w, acc.w);
        acc.x = fmaf(n1, v1.x, acc.x); acc.y = fmaf(n1, v1.y, acc.y);
        acc.z = fmaf(n1, v1.z, acc.z); acc.w = fmaf(n1, v1.w, acc.w);
        acc.x = fmaf(n2, v2.x, acc.x); acc.y = fmaf(n2, v2.y, acc.y);
        acc.z = fmaf(n2, v2.z, acc.z); acc.w = fmaf(n2, v2.w, acc.w);
        acc.x = fmaf(n3, v3.x, acc.x); acc.y = fmaf(n3, v3.y, acc.y);
        acc.z = fmaf(n3, v3.z, acc.z); acc.w = fmaf(n3, v3.w, acc.w);
    }
    for (; j < end; j++) {
        int2 e0 = __ldg(&g_edge[j]);
        float4 v0 = __ldg(&g_h4[(size_t)e0.x * 16 + l16]);
        float n0 = __int_as_float(e0.y);
        acc.x = fmaf(n0, v0.x, acc.x); acc.y = fmaf(n0, v0.y, acc.y);
        acc.z = fmaf(n0, v0.z, acc.z); acc.w = fmaf(n0, v0.w, acc.w);
    }

    float4 bb = __ldg(((const float4*)b) + l16);
    acc.x += bb.x; acc.y += bb.y; acc.z += bb.z; acc.w += bb.w;
    if (relu) {
        acc.x = fmaxf(acc.x, 0.0f); acc.y = fmaxf(acc.y, 0.0f);
        acc.z = fmaxf(acc.z, 0.0f); acc.w = fmaxf(acc.w, 0.0f);
    } else {
        acc.x = f_sig(acc.x); acc.y = f_sig(acc.y);
        acc.z = f_sig(acc.z); acc.w = f_sig(acc.w);
    }
    g_gc4[(size_t)node * 16 + l16] = acc;
}

// ---------------- fused GRU gates (scalar, 8 rows/epoch, 2 blocks/SM) ----------------
#define GROWS 8
__global__ __launch_bounds__(192, 2) void k_gates(const float* __restrict__ Hm,
                                               const float* __restrict__ Wz, const float* __restrict__ bz,
                                               const float* __restrict__ Wr, const float* __restrict__ br,
                                               const float* __restrict__ Wh, const float* __restrict__ bh,
                                               float* __restrict__ out) {
    int t = threadIdx.x;
    int gate = t >> 6;
    int c = t & 63;
    const float* W = (gate == 0) ? Wz : (gate == 1) ? Wr : Wh;
    float bias = ((gate == 0) ? bz : (gate == 1) ? br : bh)[c];
    float w[128];
#pragma unroll
    for (int k = 0; k < 128; k++) w[k] = __ldg(&W[k * 64 + c]);

    __shared__ float s_x[GROWS][128];    // [0:64) GC, [64:128) H
    __shared__ float s_zr[GROWS][128];   // [0:64) Z, [64:128) R
    __shared__ float s_ht[GROWS][64];

    const float* gc = (const float*)g_gc4;
    const int groups = NN / GROWS;       // 12500

    for (int g = blockIdx.x; g < groups; g += gridDim.x) {
        int r0 = g * GROWS;
        __syncthreads();
        if (t < 128) {
            const float* base = (t < 64) ? (gc + (size_t)r0 * 64 + t)
                                         : (Hm + (size_t)r0 * 64 + (t - 64));
#pragma unroll
            for (int rr = 0; rr < GROWS; rr++) s_x[rr][t] = __ldg(base + rr * 64);
        }
        __syncthreads();

        float acc[GROWS];
#pragma unroll
        for (int rr = 0; rr < GROWS; rr++) acc[rr] = bias;

        if (gate < 2) {
#pragma unroll
            for (int k4 = 0; k4 < 32; k4++) {
#pragma unroll
                for (int rr = 0; rr < GROWS; rr++) {
                    float4 v = ((const float4*)s_x[rr])[k4];
                    acc[rr] = fmaf(v.x, w[4 * k4 + 0], acc[rr]);
                    acc[rr] = fmaf(v.y, w[4 * k4 + 1], acc[rr]);
                    acc[rr] = fmaf(v.z, w[4 * k4 + 2], acc[rr]);
                    acc[rr] = fmaf(v.w, w[4 * k4 + 3], acc[rr]);
                }
            }
#pragma unroll
            for (int rr = 0; rr < GROWS; rr++)
                s_zr[rr][gate * 64 + c] = f_sig(acc[rr]);
        } else {
#pragma unroll
            for (int k4 = 0; k4 < 16; k4++) {      // GC half
#pragma unroll
                for (int rr = 0; rr < GROWS; rr++) {
                    float4 v = ((const float4*)s_x[rr])[k4];
                    acc[rr] = fmaf(v.x, w[4 * k4 + 0], acc[rr]);
                    acc[rr] = fmaf(v.y, w[4 * k4 + 1], acc[rr]);
                    acc[rr] = fmaf(v.z, w[4 * k4 + 2], acc[rr]);
                    acc[rr] = fmaf(v.w, w[4 * k4 + 3], acc[rr]);
                }
            }
        }
        __syncthreads();

        if (gate == 2) {
#pragma unroll
            for (int k4 = 0; k4 < 16; k4++) {      // (H*R) half
#pragma unroll
                for (int rr = 0; rr < GROWS; rr++) {
                    float4 hv = ((const float4*)s_x[rr])[16 + k4];
                    float4 rv = ((const float4*)s_zr[rr])[16 + k4];
                    acc[rr] = fmaf(hv.x * rv.x, w[64 + 4 * k4 + 0], acc[rr]);
                    acc[rr] = fmaf(hv.y * rv.y, w[64 + 4 * k4 + 1], acc[rr]);
                    acc[rr] = fmaf(hv.z * rv.z, w[64 + 4 * k4 + 2], acc[rr]);
                    acc[rr] = fmaf(hv.w * rv.w, w[64 + 4 * k4 + 3], acc[rr]);
                }
            }
#pragma unroll
            for (int rr = 0; rr < GROWS; rr++) s_ht[rr][c] = f_tanh(acc[rr]);
        }
        __syncthreads();

        if (gate == 0) {
#pragma unroll
            for (int rr = 0; rr < GROWS; rr++) {
                float z  = s_zr[rr][c];
                float hv = s_x[rr][64 + c];
                out[(size_t)(r0 + rr) * 64 + c] = z * hv + (1.0f - z) * s_ht[rr][c];
            }
        }
    }
}

// ---------------- launch ----------------
extern "C" void kernel_launch(void* const* d_in, const int* in_sizes, int n_in,
                              void* d_out, int out_size) {
    const float* X  = (const float*)d_in[0];
    const int*   EI = (const int*)d_in[1];     // int32 (JAX default x64 disabled)
    const float* EW = (const float*)d_in[2];
    const float* H  = (const float*)d_in[3];
    const float* W1 = (const float*)d_in[4];
    const float* b1 = (const float*)d_in[5];
    const float* W2 = (const float*)d_in[6];
    const float* b2 = (const float*)d_in[7];
    const float* Wz = (const float*)d_in[8];
    const float* bz = (const float*)d_in[9];
    const float* Wr = (const float*)d_in[10];
    const float* br = (const float*)d_in[11];
    const float* Wh = (const float*)d_in[12];
    const float* bh = (const float*)d_in[13];
    float* out = (float*)d_out;

    const int TB = 256;
    const int nBlkN   = (NN + TB - 1) / TB;
    const int nBlkE2  = (EE / 2 + TB - 1) / TB;
    const int nBlkGat = (NN * 16 + TB - 1) / TB;

    // prep + layer pipeline (k_gemm_x at launch #4 for direct verification)
    k_init<<<nBlkN, TB>>>();
    k_count<<<nBlkE2, TB>>>(EI, EW);
    k_scan1<<<SCAN_NB, SCAN_BS>>>();
    k_gemm_x<<<1024, TB>>>(X, W1);
    k_scan2<<<1, 256>>>();
    k_scan3<<<SCAN_NB, SCAN_BS>>>();
    k_scatter<<<nBlkE2, TB>>>(EI, EW);

    k_gather<<<nBlkGat, TB>>>(b1, 1);   // relu -> g_gc4

    k_gemm_gc<<<1024, TB>>>(W2);
    k_gather<<<nBlkGat, TB>>>(b2, 0);   // sigmoid -> g_gc4

    k_gates<<<592, 192>>>(H, Wz, bz, Wr, br, Wh, bh, out);
}

// round 16
// speedup vs baseline: 1.0922x; 1.0922x over previous
#include <cuda_runtime.h>
#include <cuda_bf16.h>
#include <math.h>

#define NN 100000
#define EE 1600000

#define SCAN_BS 512
#define SCAN_NB ((NN + SCAN_BS - 1) / SCAN_BS)   // 196

// ---------------- scratch (device globals; no allocation allowed) ----------------
__device__ float  g_deg[NN];
__device__ float  g_dinv[NN];
__device__ int    g_cnt[NN];
__device__ int    g_ptr[NN];
__device__ int    g_cur[NN];
__device__ int    g_bsum[SCAN_NB];
__device__ int    g_boff[SCAN_NB];
__device__ int2   g_edge[EE];       // CSR slot: {src, float_bits(norm)}
__device__ float4 g_h4[NN * 16];    // GEMM output (messages)
__device__ float4 g_gc4[NN * 16];   // aggregated + activated output

// ---------------- fast activations (2-ulp class, saturation-safe) ----------------
__device__ __forceinline__ float f_sig(float x) {
    return __fdividef(1.0f, 1.0f + __expf(-x));
}
__device__ __forceinline__ float f_tanh(float x) {
    return 1.0f - __fdividef(2.0f, __expf(2.0f * x) + 1.0f);
}

// ---------------- cp.async helpers ----------------
__device__ __forceinline__ void cp_async16(void* smem_dst, const void* gsrc) {
    unsigned s = (unsigned)__cvta_generic_to_shared(smem_dst);
    asm volatile("cp.async.cg.shared.global [%0], [%1], 16;" :: "r"(s), "l"(gsrc));
}
__device__ __forceinline__ void cp_commit() {
    asm volatile("cp.async.commit_group;");
}
__device__ __forceinline__ void cp_wait0() {
    asm volatile("cp.async.wait_group 0;");
}

// ---------------- prep ----------------
__global__ void k_init() {
    int i = blockIdx.x * blockDim.x + threadIdx.x;
    if (i < NN) { g_deg[i] = 1.0f; g_cnt[i] = 0; }
}

__global__ void k_count(const int* __restrict__ ei, const float* __restrict__ w) {
    int p = blockIdx.x * blockDim.x + threadIdx.x;
    if (p < EE / 2) {
        int2   c2 = __ldg((const int2*)(ei + EE) + p);
        float2 w2 = __ldg((const float2*)w + p);
        atomicAdd(&g_deg[c2.x], w2.x);
        atomicAdd(&g_cnt[c2.x], 1);
        atomicAdd(&g_deg[c2.y], w2.y);
        atomicAdd(&g_cnt[c2.y], 1);
    }
}

__global__ __launch_bounds__(SCAN_BS) void k_scan1() {
    __shared__ int sh[SCAN_BS];
    int t = threadIdx.x;
    int i = blockIdx.x * SCAN_BS + t;
    if (i < NN) {
        float d = g_deg[i];
        g_dinv[i] = (d > 0.0f) ? rsqrtf(d) : 0.0f;
    }
    int v = (i < NN) ? g_cnt[i] : 0;
    sh[t] = v;
    __syncthreads();
#pragma unroll
    for (int off = 1; off < SCAN_BS; off <<= 1) {
        int x = (t >= off) ? sh[t - off] : 0;
        __syncthreads();
        sh[t] += x;
        __syncthreads();
    }
    if (i < NN) g_ptr[i] = sh[t] - v;
    if (t == SCAN_BS - 1) g_bsum[blockIdx.x] = sh[t];
}

__global__ __launch_bounds__(256) void k_scan2() {
    __shared__ int sh[256];
    int t = threadIdx.x;
    int v = (t < SCAN_NB) ? g_bsum[t] : 0;
    sh[t] = v;
    __syncthreads();
#pragma unroll
    for (int off = 1; off < 256; off <<= 1) {
        int x = (t >= off) ? sh[t - off] : 0;
        __syncthreads();
        sh[t] += x;
        __syncthreads();
    }
    if (t < SCAN_NB) g_boff[t] = sh[t] - v;
}

__global__ __launch_bounds__(SCAN_BS) void k_scan3() {
    int i = blockIdx.x * SCAN_BS + threadIdx.x;
    if (i < NN) {
        int p = g_ptr[i] + g_boff[blockIdx.x];
        g_ptr[i] = p;
        g_cur[i] = p;
    }
}

__global__ void k_scatter(const int* __restrict__ ei, const float* __restrict__ w) {
    int p = blockIdx.x * blockDim.x + threadIdx.x;
    if (p < EE / 2) {
        int2   r2 = __ldg((const int2*)ei + p);
        int2   c2 = __ldg((const int2*)(ei + EE) + p);
        float2 w2 = __ldg((const float2*)w + p);
        float n0 = g_dinv[r2.x] * w2.x * g_dinv[c2.x];
        float n1 = g_dinv[r2.y] * w2.y * g_dinv[c2.y];
        int s0 = atomicAdd(&g_cur[c2.x], 1);
        int s1 = atomicAdd(&g_cur[c2.y], 1);
        g_edge[s0] = make_int2(r2.x, __float_as_int(n0));
        g_edge[s1] = make_int2(r2.y, __float_as_int(n1));
    }
}

// ---------------- dense GEMM: cp.async double-buffered smem pipeline ----------------
// R15 profile: 33.6us (was 47.5 serial, 88 un-staged). Keep.
__device__ __forceinline__ void gemm64_body(const float* __restrict__ x,
                                            const float* __restrict__ W) {
    int t   = threadIdx.x;
    int c   = t & 63;
    int sub = t >> 6;                 // 0..3
    float w[64];
#pragma unroll
    for (int k = 0; k < 64; k++) w[k] = __ldg(&W[k * 64 + c]);

    __shared__ float4 s_x[2][16][16]; // 2 x (16 rows x 64 floats)

    float* __restrict__ hout = (float*)g_h4;
    const int tiles = NN / 16;        // 6250
    int row16 = t >> 4, col16 = t & 15;

    int tile = blockIdx.x;
    if (tile < tiles)
        cp_async16(&s_x[0][row16][col16],
                   (const float4*)(x + (size_t)(tile * 16 + row16) * 64) + col16);
    cp_commit();

    int buf = 0;
    for (; tile < tiles; tile += gridDim.x) {
        cp_wait0();
        __syncthreads();               // buffer `buf` filled; prev compute on buf^1 done
        int next = tile + gridDim.x;
        if (next < tiles)
            cp_async16(&s_x[buf ^ 1][row16][col16],
                       (const float4*)(x + (size_t)(next * 16 + row16) * 64) + col16);
        cp_commit();

        float acc[4] = {0.0f, 0.0f, 0.0f, 0.0f};
#pragma unroll
        for (int k4 = 0; k4 < 16; k4++) {
#pragma unroll
            for (int rr = 0; rr < 4; rr++) {
                float4 v = s_x[buf][sub + rr * 4][k4];   // LDS broadcast
                acc[rr] = fmaf(v.x, w[4 * k4 + 0], acc[rr]);
                acc[rr] = fmaf(v.y, w[4 * k4 + 1], acc[rr]);
                acc[rr] = fmaf(v.z, w[4 * k4 + 2], acc[rr]);
                acc[rr] = fmaf(v.w, w[4 * k4 + 3], acc[rr]);
            }
        }
        int base = tile * 16;
#pragma unroll
        for (int rr = 0; rr < 4; rr++)
            hout[(size_t)(base + sub + rr * 4) * 64 + c] = acc[rr];
        buf ^= 1;
    }
}

__global__ __launch_bounds__(256) void k_gemm_x(const float* __restrict__ x,
                                                const float* __restrict__ W) {
    gemm64_body(x, W);
}

__global__ __launch_bounds__(256) void k_gemm_gc(const float* __restrict__ W) {
    gemm64_body((const float*)g_gc4, W);
}

// ---------------- fused aggregation (R9, L2-BW bound) ----------------
__global__ __launch_bounds__(256) void k_gather(const float* __restrict__ b, int relu) {
    int t = blockIdx.x * blockDim.x + threadIdx.x;
    int node = t >> 4;
    if (node >= NN) return;
    int l16 = t & 15;

    float s = g_dinv[node];
    s = s * s;
    float4 acc = g_h4[(size_t)node * 16 + l16];
    acc.x *= s; acc.y *= s; acc.z *= s; acc.w *= s;

    int j   = g_ptr[node];
    int end = g_cur[node];

    for (; j + 3 < end; j += 4) {
        int2 e0 = __ldg(&g_edge[j]);
        int2 e1 = __ldg(&g_edge[j + 1]);
        int2 e2 = __ldg(&g_edge[j + 2]);
        int2 e3 = __ldg(&g_edge[j + 3]);
        float4 v0 = __ldg(&g_h4[(size_t)e0.x * 16 + l16]);
        float4 v1 = __ldg(&g_h4[(size_t)e1.x * 16 + l16]);
        float4 v2 = __ldg(&g_h4[(size_t)e2.x * 16 + l16]);
        float4 v3 = __ldg(&g_h4[(size_t)e3.x * 16 + l16]);
        float n0 = __int_as_float(e0.y), n1 = __int_as_float(e1.y);
        float n2 = __int_as_float(e2.y), n3 = __int_as_float(e3.y);
        acc.x = fmaf(n0, v0.x, acc.x); acc.y = fmaf(n0, v0.y, acc.y);
        acc.z = fmaf(n0, v0.z, acc.z); acc.w = fmaf(n0, v0.w, acc.w);
        acc.x = fmaf(n1, v1.x, acc.x); acc.y = fmaf(n1, v1.y, acc.y);
        acc.z = fmaf(n1, v1.z, acc.z); acc.w = fmaf(n1, v1.w, acc.w);
        acc.x = fmaf(n2, v2.x, acc.x); acc.y = fmaf(n2, v2.y, acc.y);
        acc.z = fmaf(n2, v2.z, acc.z); acc.w = fmaf(n2, v2.w, acc.w);
        acc.x = fmaf(n3, v3.x, acc.x); acc.y = fmaf(n3, v3.y, acc.y);
        acc.z = fmaf(n3, v3.z, acc.z); acc.w = fmaf(n3, v3.w, acc.w);
    }
    for (; j < end; j++) {
        int2 e0 = __ldg(&g_edge[j]);
        float4 v0 = __ldg(&g_h4[(size_t)e0.x * 16 + l16]);
        float n0 = __int_as_float(e0.y);
        acc.x = fmaf(n0, v0.x, acc.x); acc.y = fmaf(n0, v0.y, acc.y);
        acc.z = fmaf(n0, v0.z, acc.z); acc.w = fmaf(n0, v0.w, acc.w);
    }

    float4 bb = __ldg(((const float4*)b) + l16);
    acc.x += bb.x; acc.y += bb.y; acc.z += bb.z; acc.w += bb.w;
    if (relu) {
        acc.x = fmaxf(acc.x, 0.0f); acc.y = fmaxf(acc.y, 0.0f);
        acc.z = fmaxf(acc.z, 0.0f); acc.w = fmaxf(acc.w, 0.0f);
    } else {
        acc.x = f_sig(acc.x); acc.y = f_sig(acc.y);
        acc.z = f_sig(acc.z); acc.w = f_sig(acc.w);
    }
    g_gc4[(size_t)node * 16 + l16] = acc;
}

// ---------------- fused GRU gates (R13 config: scalar, 8 rows/epoch) ----------------
// R15 lesson: __launch_bounds__(192,2) capped regs at 170 -> spilled w[128] -> +50us.
#define GROWS 8
__global__ __launch_bounds__(192) void k_gates(const float* __restrict__ Hm,
                                               const float* __restrict__ Wz, const float* __restrict__ bz,
                                               const float* __restrict__ Wr, const float* __restrict__ br,
                                               const float* __restrict__ Wh, const float* __restrict__ bh,
                                               float* __restrict__ out) {
    int t = threadIdx.x;
    int gate = t >> 6;
    int c = t & 63;
    const float* W = (gate == 0) ? Wz : (gate == 1) ? Wr : Wh;
    float bias = ((gate == 0) ? bz : (gate == 1) ? br : bh)[c];
    float w[128];
#pragma unroll
    for (int k = 0; k < 128; k++) w[k] = __ldg(&W[k * 64 + c]);

    __shared__ float s_x[GROWS][128];    // [0:64) GC, [64:128) H
    __shared__ float s_zr[GROWS][128];   // [0:64) Z, [64:128) R
    __shared__ float s_ht[GROWS][64];

    const float* gc = (const float*)g_gc4;
    const int groups = NN / GROWS;       // 12500

    for (int g = blockIdx.x; g < groups; g += gridDim.x) {
        int r0 = g * GROWS;
        __syncthreads();
        if (t < 128) {
            const float* base = (t < 64) ? (gc + (size_t)r0 * 64 + t)
                                         : (Hm + (size_t)r0 * 64 + (t - 64));
#pragma unroll
            for (int rr = 0; rr < GROWS; rr++) s_x[rr][t] = __ldg(base + rr * 64);
        }
        __syncthreads();

        float acc[GROWS];
#pragma unroll
        for (int rr = 0; rr < GROWS; rr++) acc[rr] = bias;

        if (gate < 2) {
#pragma unroll
            for (int k4 = 0; k4 < 32; k4++) {
#pragma unroll
                for (int rr = 0; rr < GROWS; rr++) {
                    float4 v = ((const float4*)s_x[rr])[k4];
                    acc[rr] = fmaf(v.x, w[4 * k4 + 0], acc[rr]);
                    acc[rr] = fmaf(v.y, w[4 * k4 + 1], acc[rr]);
                    acc[rr] = fmaf(v.z, w[4 * k4 + 2], acc[rr]);
                    acc[rr] = fmaf(v.w, w[4 * k4 + 3], acc[rr]);
                }
            }
#pragma unroll
            for (int rr = 0; rr < GROWS; rr++)
                s_zr[rr][gate * 64 + c] = f_sig(acc[rr]);
        } else {
#pragma unroll
            for (int k4 = 0; k4 < 16; k4++) {      // GC half
#pragma unroll
                for (int rr = 0; rr < GROWS; rr++) {
                    float4 v = ((const float4*)s_x[rr])[k4];
                    acc[rr] = fmaf(v.x, w[4 * k4 + 0], acc[rr]);
                    acc[rr] = fmaf(v.y, w[4 * k4 + 1], acc[rr]);
                    acc[rr] = fmaf(v.z, w[4 * k4 + 2], acc[rr]);
                    acc[rr] = fmaf(v.w, w[4 * k4 + 3], acc[rr]);
                }
            }
        }
        __syncthreads();

        if (gate == 2) {
#pragma unroll
            for (int k4 = 0; k4 < 16; k4++) {      // (H*R) half
#pragma unroll
                for (int rr = 0; rr < GROWS; rr++) {
                    float4 hv = ((const float4*)s_x[rr])[16 + k4];
                    float4 rv = ((const float4*)s_zr[rr])[16 + k4];
                    acc[rr] = fmaf(hv.x * rv.x, w[64 + 4 * k4 + 0], acc[rr]);
                    acc[rr] = fmaf(hv.y * rv.y, w[64 + 4 * k4 + 1], acc[rr]);
                    acc[rr] = fmaf(hv.z * rv.z, w[64 + 4 * k4 + 2], acc[rr]);
                    acc[rr] = fmaf(hv.w * rv.w, w[64 + 4 * k4 + 3], acc[rr]);
                }
            }
#pragma unroll
            for (int rr = 0; rr < GROWS; rr++) s_ht[rr][c] = f_tanh(acc[rr]);
        }
        __syncthreads();

        if (gate == 0) {
#pragma unroll
            for (int rr = 0; rr < GROWS; rr++) {
                float z  = s_zr[rr][c];
                float hv = s_x[rr][64 + c];
                out[(size_t)(r0 + rr) * 64 + c] = z * hv + (1.0f - z) * s_ht[rr][c];
            }
        }
    }
}

// ---------------- launch ----------------
extern "C" void kernel_launch(void* const* d_in, const int* in_sizes, int n_in,
                              void* d_out, int out_size) {
    const float* X  = (const float*)d_in[0];
    const int*   EI = (const int*)d_in[1];     // int32 (JAX default x64 disabled)
    const float* EW = (const float*)d_in[2];
    const float* H  = (const float*)d_in[3];
    const float* W1 = (const float*)d_in[4];
    const float* b1 = (const float*)d_in[5];
    const float* W2 = (const float*)d_in[6];
    const float* b2 = (const float*)d_in[7];
    const float* Wz = (const float*)d_in[8];
    const float* bz = (const float*)d_in[9];
    const float* Wr = (const float*)d_in[10];
    const float* br = (const float*)d_in[11];
    const float* Wh = (const float*)d_in[12];
    const float* bh = (const float*)d_in[13];
    float* out = (float*)d_out;

    const int TB = 256;
    const int nBlkN   = (NN + TB - 1) / TB;
    const int nBlkE2  = (EE / 2 + TB - 1) / TB;
    const int nBlkGat = (NN * 16 + TB - 1) / TB;

    // prep + layer pipeline
    k_init<<<nBlkN, TB>>>();
    k_count<<<nBlkE2, TB>>>(EI, EW);
    k_scan1<<<SCAN_NB, SCAN_BS>>>();
    k_gemm_x<<<1024, TB>>>(X, W1);
    k_scan2<<<1, 256>>>();
    k_scan3<<<SCAN_NB, SCAN_BS>>>();
    k_scatter<<<nBlkE2, TB>>>(EI, EW);

    k_gather<<<nBlkGat, TB>>>(b1, 1);   // relu -> g_gc4

    k_gemm_gc<<<1024, TB>>>(W2);
    k_gather<<<nBlkGat, TB>>>(b2, 0);   // sigmoid -> g_gc4

    k_gates<<<592, 192>>>(H, Wz, bz, Wr, br, Wh, bh, out);
}